// round 15
// baseline (speedup 1.0000x reference)
#include <cuda_runtime.h>
#include <cuda_fp16.h>
#include <math.h>
#include <stdint.h>

#define N_TOKENS 16384
#define D_MODEL  4096
#define N_EXP    64
#define LB_COEF  0.01f

#define KC     32
#define NCHUNK (D_MODEL / KC)      // 128
#define TM     32
#define NCTA   (N_TOKENS / TM)     // 512
#define NTHR   128

// layout (PA=20 proven): A1[32], A2[32], B1[64], B2[64] rows x 20 words
#define PA      20
#define A1_OFF  0
#define A2_OFF  (32 * PA)          // 640
#define B1_OFF  (2 * 32 * PA)      // 1280
#define B2_OFF  (B1_OFF + 64 * PA) // 2560
#define STAGE_W (B2_OFF + 64 * PA) // 3840 words = 15360 B
#define DYN_BYTES (2 * STAGE_W * 4)   // 30720 B

#define WSCALE   256.0f
#define WDESCALE 0.00390625f       // 2^-8

// ---------------- helpers ----------------
static __device__ __forceinline__ uint32_t smem_u32(const void* p) {
    uint32_t a;
    asm("{ .reg .u64 t; cvta.to.shared.u64 t, %1; cvt.u32.u64 %0, t; }" : "=r"(a) : "l"(p));
    return a;
}
#define CPASYNC16(dst, src) \
    asm volatile("cp.async.cg.shared.global [%0], [%1], 16;" :: "r"(dst), "l"(src))
#define CPCOMMIT()  asm volatile("cp.async.commit_group;" ::: "memory")
#define CPWAIT0()   asm volatile("cp.async.wait_group 0;" ::: "memory")

#define LDSM4(r, addr)                                                        \
    asm volatile("ldmatrix.sync.aligned.m8n8.x4.shared.b16 {%0,%1,%2,%3}, [%4];" \
        : "=r"((r)[0]), "=r"((r)[1]), "=r"((r)[2]), "=r"((r)[3]) : "r"(addr))

// split float4 -> h1 pairs (uint2) + residual h2 pairs (uint2)
static __device__ __forceinline__ void split4(float4 v, uint2& h1, uint2& h2) {
    __half a0 = __float2half_rn(v.x);
    __half a1 = __float2half_rn(v.y);
    __half a2 = __float2half_rn(v.z);
    __half a3 = __float2half_rn(v.w);
    __half b0 = __float2half_rn(v.x - __half2float(a0));
    __half b1 = __float2half_rn(v.y - __half2float(a1));
    __half b2 = __float2half_rn(v.z - __half2float(a2));
    __half b3 = __float2half_rn(v.w - __half2float(a3));
    __half2 p01 = __halves2half2(a0, a1);
    __half2 p23 = __halves2half2(a2, a3);
    __half2 q01 = __halves2half2(b0, b1);
    __half2 q23 = __halves2half2(b2, b3);
    h1.x = *reinterpret_cast<uint32_t*>(&p01);
    h1.y = *reinterpret_cast<uint32_t*>(&p23);
    h2.x = *reinterpret_cast<uint32_t*>(&q01);
    h2.y = *reinterpret_cast<uint32_t*>(&q23);
}

#define MMAH(d, a, b)                                                    \
    asm volatile(                                                        \
        "mma.sync.aligned.m16n8k16.row.col.f32.f16.f16.f32 "             \
        "{%0,%1,%2,%3}, {%4,%5,%6,%7}, {%8,%9}, {%0,%1,%2,%3};"          \
        : "+f"((d)[0]), "+f"((d)[1]), "+f"((d)[2]), "+f"((d)[3])         \
        : "r"((a)[0]), "r"((a)[1]), "r"((a)[2]), "r"((a)[3]),            \
          "r"((b)[0]), "r"((b)[1]))

// ---------------- device scratch ----------------
__device__ uint32_t g_b1[N_EXP * (D_MODEL / 2)];   // pre-split gw*256, h1 pairs
__device__ uint32_t g_b2[N_EXP * (D_MODEL / 2)];   // residual h2 pairs
__device__ float g_psum[N_EXP];
__device__ int   g_cnt[N_EXP];
__device__ int   g_ticket;

// ---------------- prep: split gate_w*256 into f16 pair tables ----------------
__global__ void prep_kernel(const float* __restrict__ gw) {
    int i = blockIdx.x * blockDim.x + threadIdx.x;
    if (i < N_EXP * (D_MODEL / 2)) {
        float x0 = gw[2 * i]     * WSCALE;
        float x1 = gw[2 * i + 1] * WSCALE;
        __half a0 = __float2half_rn(x0);
        __half a1 = __float2half_rn(x1);
        __half b0 = __float2half_rn(x0 - __half2float(a0));
        __half b1 = __float2half_rn(x1 - __half2float(a1));
        __half2 p = __halves2half2(a0, a1);
        __half2 q = __halves2half2(b0, b1);
        g_b1[i] = *reinterpret_cast<uint32_t*>(&p);
        g_b2[i] = *reinterpret_cast<uint32_t*>(&q);
    }
}

// ---------------- fused GEMM (2xFP16 3-term, ldmatrix, 4 CTAs/SM) --------------
// 128 threads = 4 warps. CTA tile 32x64. Warp tile 32x32; wg = k16-half, wn = n-half.
__global__ __launch_bounds__(NTHR, 4)
void router_kernel(const float* __restrict__ x,
                   float* __restrict__ out)
{
    extern __shared__ float dynsm[];
    __shared__ int   cb[N_EXP];
    __shared__ float s_red[N_EXP];
    __shared__ float s_m[TM];
    __shared__ float s_inv[TM];
    __shared__ int   s_islast;

    const int tid  = threadIdx.x;
    const int t0   = blockIdx.x * TM;
    const int lane = tid & 31;
    const int wid  = tid >> 5;
    const int wg   = wid >> 1;          // k16-half within the 32-k chunk
    const int wn   = wid & 1;           // expert half (n base wn*32)
    const int lr   = lane >> 2;
    const int lc   = lane & 3;

    if (tid < N_EXP) cb[tid] = 0;

    uint32_t* smw = (uint32_t*)dynsm;
    const uint32_t sbase = smem_u32(dynsm);

    // ---- loop-invariant ldmatrix lane addresses
    const int aRow = lane & 15;                       // m tile = all 32 rows (mi step +16)
    const uint32_t aBase = sbase + (uint32_t)((aRow * PA + wg * 8) * 4) + ((lane >> 4) << 4);
    const int bRow = wn * 32 + ((lane >> 4) << 3) + (lane & 7);
    const uint32_t bBase = sbase + (uint32_t)((bRow * PA + wg * 8) * 4) + (((lane >> 3) & 1) << 4);

    const uint32_t aA1 = aBase + A1_OFF * 4;
    const uint32_t aA2 = aBase + A2_OFF * 4;
    const uint32_t bB1 = bBase + B1_OFF * 4;
    const uint32_t bB2 = bBase + B2_OFF * 4;
    const uint32_t MI_STEP = 16 * PA * 4;   // +16 rows

    // A fill mapping: rA = tid>>2 (0..31), f4 slots sA and sA+4
    const int rA = tid >> 2;
    const int sA = tid & 3;
    // B fill mapping: 2 x (row, quarter) per table
    const int rB0 = tid >> 1;              // rows 0..63
    const int qB0 = (tid & 1) * 2;         // quarters 0/2 then +1 inside

    const float4* x4 = (const float4*)x;     // row pitch 1024 f4
    const size_t xo = (size_t)(t0 + rA) * 1024 + sA;

    // ---- prologue: fill stage 0
    {
        const uint32_t doff0 = (rB0 * PA + 4 * qB0) * 4;
        const size_t so0 = (size_t)rB0 * (D_MODEL / 2) + 4 * qB0;
        CPASYNC16(sbase + B1_OFF * 4 + doff0,      g_b1 + so0);
        CPASYNC16(sbase + B1_OFF * 4 + doff0 + 16, g_b1 + so0 + 4);
        CPASYNC16(sbase + B2_OFF * 4 + doff0,      g_b2 + so0);
        CPASYNC16(sbase + B2_OFF * 4 + doff0 + 16, g_b2 + so0 + 4);
        CPCOMMIT();
        float4 v0 = x4[xo];
        float4 v1 = x4[xo + 4];
        uint2 h1, h2;
        split4(v0, h1, h2);
        *(uint2*)(smw + A1_OFF + rA * PA + 2 * sA) = h1;
        *(uint2*)(smw + A2_OFF + rA * PA + 2 * sA) = h2;
        split4(v1, h1, h2);
        *(uint2*)(smw + A1_OFF + rA * PA + 2 * sA + 8) = h1;
        *(uint2*)(smw + A2_OFF + rA * PA + 2 * sA + 8) = h2;
        CPWAIT0();
    }
    __syncthreads();

    float acc[2][4][4];
#pragma unroll
    for (int mi = 0; mi < 2; mi++)
#pragma unroll
        for (int ni = 0; ni < 4; ni++)
#pragma unroll
            for (int j = 0; j < 4; j++) acc[mi][ni][j] = 0.0f;

    // ---- main loop: 128 chunks of 32-k, double-buffered, one bar each
    for (int c = 0; c < NCHUNK; c++) {
        float4 n0, n1;
        if (c + 1 < NCHUNK) {
            // B(c+1) via cp.async
            const uint32_t stb = sbase + (((c + 1) & 1) * STAGE_W) * 4;
            const uint32_t doff = (rB0 * PA + 4 * qB0) * 4;
            const size_t so = (size_t)rB0 * (D_MODEL / 2) + (c + 1) * 16 + 4 * qB0;
            CPASYNC16(stb + B1_OFF * 4 + doff,      g_b1 + so);
            CPASYNC16(stb + B1_OFF * 4 + doff + 16, g_b1 + so + 4);
            CPASYNC16(stb + B2_OFF * 4 + doff,      g_b2 + so);
            CPASYNC16(stb + B2_OFF * 4 + doff + 16, g_b2 + so + 4);
            // A(c+1) prefetch to regs
            const size_t d0 = (size_t)(c + 1) * 8;
            n0 = x4[xo + d0]; n1 = x4[xo + d0 + 4];
        }
        CPCOMMIT();

        // compute current chunk via ldmatrix
        const uint32_t so = ((c & 1) * STAGE_W) * 4;
        {
            uint32_t a1[2][4], a2[2][4], bq1[2][4], bq2[2][4];
            LDSM4(a1[0], aA1 + so);
            LDSM4(a1[1], aA1 + so + MI_STEP);
            LDSM4(a2[0], aA2 + so);
            LDSM4(a2[1], aA2 + so + MI_STEP);
            LDSM4(bq1[0], bB1 + so);
            LDSM4(bq1[1], bB1 + so + MI_STEP);
            LDSM4(bq2[0], bB2 + so);
            LDSM4(bq2[1], bB2 + so + MI_STEP);
#pragma unroll
            for (int ni = 0; ni < 4; ni++) {
                uint32_t b1[2] = { bq1[ni >> 1][(ni & 1) * 2], bq1[ni >> 1][(ni & 1) * 2 + 1] };
                uint32_t b2[2] = { bq2[ni >> 1][(ni & 1) * 2], bq2[ni >> 1][(ni & 1) * 2 + 1] };
#pragma unroll
                for (int mi = 0; mi < 2; mi++) {
                    MMAH(acc[mi][ni], a1[mi], b1);
                    MMAH(acc[mi][ni], a2[mi], b1);
                    MMAH(acc[mi][ni], a1[mi], b2);
                    // a2*b2 dropped: ~2^-22 relative, below noise floor
                }
            }
        }

        // A(c+1): split + STS into the other stage
        if (c + 1 < NCHUNK) {
            uint32_t* stn = smw + ((c + 1) & 1) * STAGE_W;
            uint2 h1, h2;
            split4(n0, h1, h2);
            *(uint2*)(stn + A1_OFF + rA * PA + 2 * sA) = h1;
            *(uint2*)(stn + A2_OFF + rA * PA + 2 * sA) = h2;
            split4(n1, h1, h2);
            *(uint2*)(stn + A1_OFF + rA * PA + 2 * sA + 8) = h1;
            *(uint2*)(stn + A2_OFF + rA * PA + 2 * sA + 8) = h2;
        }
        CPWAIT0();
        __syncthreads();
    }

    // ---- merge k-half accumulators into G[32][65] (overlays stage smem)
    float* G = dynsm;
    if (wg == 0) {
#pragma unroll
        for (int mi = 0; mi < 2; mi++)
#pragma unroll
            for (int ni = 0; ni < 4; ni++) {
                int tr = mi * 16 + lr;
                int ec = wn * 32 + ni * 8 + 2 * lc;
                G[tr * 65 + ec]           = acc[mi][ni][0] * WDESCALE;
                G[tr * 65 + ec + 1]       = acc[mi][ni][1] * WDESCALE;
                G[(tr + 8) * 65 + ec]     = acc[mi][ni][2] * WDESCALE;
                G[(tr + 8) * 65 + ec + 1] = acc[mi][ni][3] * WDESCALE;
            }
    }
    __syncthreads();
    if (wg == 1) {
#pragma unroll
        for (int mi = 0; mi < 2; mi++)
#pragma unroll
            for (int ni = 0; ni < 4; ni++) {
                int tr = mi * 16 + lr;
                int ec = wn * 32 + ni * 8 + 2 * lc;
                G[tr * 65 + ec]           += acc[mi][ni][0] * WDESCALE;
                G[tr * 65 + ec + 1]       += acc[mi][ni][1] * WDESCALE;
                G[(tr + 8) * 65 + ec]     += acc[mi][ni][2] * WDESCALE;
                G[(tr + 8) * 65 + ec + 1] += acc[mi][ni][3] * WDESCALE;
            }
    }
    __syncthreads();

    // ---- epilogue phase 1: per-token max + top2
    int i1 = 0, i2 = 0;
    if (tid < TM) {
        const float* row = G + tid * 65;
        float v1 = -INFINITY, v2 = -INFINITY;
#pragma unroll 8
        for (int e = 0; e < N_EXP; e++) {
            float v = row[e];
            if (v > v1)      { v2 = v1; i2 = i1; v1 = v; i1 = e; }
            else if (v > v2) { v2 = v;  i2 = e; }
        }
        s_m[tid] = v1;
    }
    __syncthreads();

    // ---- phase 2: all threads exponentiate
#pragma unroll
    for (int i = 0; i < (TM * N_EXP) / NTHR; i++) {
        int idx = tid + i * NTHR;
        int t = idx >> 6, e = idx & 63;
        G[t * 65 + e] = expf(G[t * 65 + e] - s_m[t]);
    }
    __syncthreads();

    // ---- phase 3: per-token sums + outputs
    if (tid < TM) {
        const float* row = G + tid * 65;
        float ssum = 0.0f;
#pragma unroll 8
        for (int e = 0; e < N_EXP; e++) ssum += row[e];
        s_inv[tid] = 1.0f / ssum;

        float e1 = row[i1], e2 = row[i2];
        float rn = 1.0f / (e1 + e2);
        int tg = t0 + tid;
        out[2 * tg]     = e1 * rn;
        out[2 * tg + 1] = e2 * rn;
        out[2 * N_TOKENS + 2 * tg]     = (float)i1;
        out[2 * N_TOKENS + 2 * tg + 1] = (float)i2;
        atomicAdd(&cb[i1], 1);
    }
    __syncthreads();

    // ---- phase 4: per-expert prob sums -> global
    if (tid < N_EXP) {
        float s = 0.0f;
#pragma unroll 8
        for (int t = 0; t < TM; t++) s += G[t * 65 + tid] * s_inv[t];
        atomicAdd(&g_psum[tid], s);
        atomicAdd(&g_cnt[tid], cb[tid]);
    }

    // ---- last CTA: loss + scratch reset
    if (tid == 0) {
        __threadfence();
        int t = atomicAdd(&g_ticket, 1);
        s_islast = (t == NCTA - 1) ? 1 : 0;
    }
    __syncthreads();
    if (s_islast) {
        __threadfence();
        if (tid < N_EXP) {
            float p = *(volatile float*)&g_psum[tid];
            int   f = *(volatile int*)&g_cnt[tid];
            s_red[tid] = (float)f * p;
            g_psum[tid] = 0.0f;
            g_cnt[tid]  = 0;
        }
        __syncthreads();
        for (int st = 32; st > 0; st >>= 1) {
            if (tid < st) s_red[tid] += s_red[tid + st];
            __syncthreads();
        }
        if (tid == 0) {
            out[4 * N_TOKENS] = LB_COEF * s_red[0] * (1.0f / N_TOKENS) * (1.0f / N_TOKENS);
            g_ticket = 0;
        }
    }
}

// ---------------- launch ----------------
extern "C" void kernel_launch(void* const* d_in, const int* in_sizes, int n_in,
                              void* d_out, int out_size)
{
    const float* x  = (const float*)d_in[0];
    const float* gw = (const float*)d_in[1];
    float* out = (float*)d_out;

    cudaFuncSetAttribute(router_kernel,
                         cudaFuncAttributeMaxDynamicSharedMemorySize, DYN_BYTES);

    prep_kernel<<<(N_EXP * (D_MODEL / 2) + 255) / 256, 256>>>(gw);
    router_kernel<<<NCTA, NTHR, DYN_BYTES>>>(x, out);
}

// round 16
// speedup vs baseline: 1.2894x; 1.2894x over previous
#include <cuda_runtime.h>
#include <cuda_fp16.h>
#include <math.h>
#include <stdint.h>

#define N_TOKENS 16384
#define D_MODEL  4096
#define N_EXP    64
#define LB_COEF  0.01f

#define NCH64  (D_MODEL / 64)      // 64 iterations of 64-k
#define TM     64
#define NCTA   (N_TOKENS / TM)     // 256
#define NTHR   256

// R10-proven sub-chunk layout (32 k): 4 regions of 64 rows x (16 pair-words + 4 pad)
#define PA      20
#define A1_OFF  0
#define A2_OFF  (64 * PA)          // 1280
#define B1_OFF  (2 * 64 * PA)      // 2560
#define B2_OFF  (3 * 64 * PA)      // 3840
#define SUB_W   (4 * 64 * PA)      // 5120 words = 20 KB
#define STAGE_W (2 * SUB_W)        // 10240 words = 40 KB (two 32-k subs)
#define DYN_BYTES (2 * STAGE_W * 4)   // 81920 B

#define WSCALE   256.0f
#define WDESCALE 0.00390625f       // 2^-8

// ---------------- helpers ----------------
static __device__ __forceinline__ uint32_t smem_u32(const void* p) {
    uint32_t a;
    asm("{ .reg .u64 t; cvta.to.shared.u64 t, %1; cvt.u32.u64 %0, t; }" : "=r"(a) : "l"(p));
    return a;
}
#define CPASYNC16(dst, src) \
    asm volatile("cp.async.cg.shared.global [%0], [%1], 16;" :: "r"(dst), "l"(src))
#define CPCOMMIT()  asm volatile("cp.async.commit_group;" ::: "memory")
#define CPWAIT0()   asm volatile("cp.async.wait_group 0;" ::: "memory")

#define LDSM4(r, addr)                                                        \
    asm volatile("ldmatrix.sync.aligned.m8n8.x4.shared.b16 {%0,%1,%2,%3}, [%4];" \
        : "=r"((r)[0]), "=r"((r)[1]), "=r"((r)[2]), "=r"((r)[3]) : "r"(addr))

// split float4 -> h1 pairs (uint2) + residual h2 pairs (uint2)
static __device__ __forceinline__ void split4(float4 v, uint2& h1, uint2& h2) {
    __half a0 = __float2half_rn(v.x);
    __half a1 = __float2half_rn(v.y);
    __half a2 = __float2half_rn(v.z);
    __half a3 = __float2half_rn(v.w);
    __half b0 = __float2half_rn(v.x - __half2float(a0));
    __half b1 = __float2half_rn(v.y - __half2float(a1));
    __half b2 = __float2half_rn(v.z - __half2float(a2));
    __half b3 = __float2half_rn(v.w - __half2float(a3));
    __half2 p01 = __halves2half2(a0, a1);
    __half2 p23 = __halves2half2(a2, a3);
    __half2 q01 = __halves2half2(b0, b1);
    __half2 q23 = __halves2half2(b2, b3);
    h1.x = *reinterpret_cast<uint32_t*>(&p01);
    h1.y = *reinterpret_cast<uint32_t*>(&p23);
    h2.x = *reinterpret_cast<uint32_t*>(&q01);
    h2.y = *reinterpret_cast<uint32_t*>(&q23);
}

// main term: fp32 accumulate
#define MMAH(d, a, b)                                                    \
    asm volatile(                                                        \
        "mma.sync.aligned.m16n8k16.row.col.f32.f16.f16.f32 "             \
        "{%0,%1,%2,%3}, {%4,%5,%6,%7}, {%8,%9}, {%0,%1,%2,%3};"          \
        : "+f"((d)[0]), "+f"((d)[1]), "+f"((d)[2]), "+f"((d)[3])         \
        : "r"((a)[0]), "r"((a)[1]), "r"((a)[2]), "r"((a)[3]),            \
          "r"((b)[0]), "r"((b)[1]))

// residual terms: fp16 accumulate (C=0 start, then chain)
#define MMAH16_Z(d0, d1, a, b)                                           \
    asm volatile(                                                        \
        "mma.sync.aligned.m16n8k16.row.col.f16.f16.f16.f16 "             \
        "{%0,%1}, {%2,%3,%4,%5}, {%6,%7}, {%8,%8};"                      \
        : "=r"(d0), "=r"(d1)                                             \
        : "r"((a)[0]), "r"((a)[1]), "r"((a)[2]), "r"((a)[3]),            \
          "r"((b)[0]), "r"((b)[1]), "r"(0u))

#define MMAH16_C(d0, d1, a, b)                                           \
    asm volatile(                                                        \
        "mma.sync.aligned.m16n8k16.row.col.f16.f16.f16.f16 "             \
        "{%0,%1}, {%2,%3,%4,%5}, {%6,%7}, {%0,%1};"                      \
        : "+r"(d0), "+r"(d1)                                             \
        : "r"((a)[0]), "r"((a)[1]), "r"((a)[2]), "r"((a)[3]),            \
          "r"((b)[0]), "r"((b)[1]))

// ---------------- device scratch ----------------
__device__ uint32_t g_b1[N_EXP * (D_MODEL / 2)];   // pre-split gw*256, h1 pairs
__device__ uint32_t g_b2[N_EXP * (D_MODEL / 2)];   // residual h2 pairs
__device__ float g_psum[N_EXP];
__device__ int   g_cnt[N_EXP];
__device__ int   g_ticket;

// ---------------- prep: split gate_w*256 into f16 pair tables ----------------
__global__ void prep_kernel(const float* __restrict__ gw) {
    int i = blockIdx.x * blockDim.x + threadIdx.x;
    if (i < N_EXP * (D_MODEL / 2)) {
        float x0 = gw[2 * i]     * WSCALE;
        float x1 = gw[2 * i + 1] * WSCALE;
        __half a0 = __float2half_rn(x0);
        __half a1 = __float2half_rn(x1);
        __half b0 = __float2half_rn(x0 - __half2float(a0));
        __half b1 = __float2half_rn(x1 - __half2float(a1));
        __half2 p = __halves2half2(a0, a1);
        __half2 q = __halves2half2(b0, b1);
        g_b1[i] = *reinterpret_cast<uint32_t*>(&p);
        g_b2[i] = *reinterpret_cast<uint32_t*>(&q);
    }
}

// ---------------- fused GEMM (fp16 3-term, residuals fp16-acc) ------------------
// 256 threads = 8 warps, 2 CTAs/SM. CTA tile 64x64. Warp tile 32x32 over one k16.
__global__ __launch_bounds__(NTHR, 2)
void router_kernel(const float* __restrict__ x,
                   float* __restrict__ out)
{
    extern __shared__ float dynsm[];
    __shared__ int   cb[N_EXP];
    __shared__ float s_red[N_EXP];
    __shared__ float s_m[TM];
    __shared__ float s_inv[TM];
    __shared__ int   s_islast;

    const int tid  = threadIdx.x;
    const int t0   = blockIdx.x * TM;
    const int lane = tid & 31;
    const int wid  = tid >> 5;
    const int wg   = wid >> 2;          // k16-half within each 32-k sub-chunk
    const int widg = wid & 3;
    const int wm   = widg >> 1;
    const int wn   = widg & 1;
    const int lr   = lane >> 2;
    const int lc   = lane & 3;

    if (tid < N_EXP) cb[tid] = 0;

    uint32_t* smw = (uint32_t*)dynsm;
    const uint32_t sbase = smem_u32(dynsm);

    // ---- loop-invariant ldmatrix lane addresses
    const int aRow = wm * 32 + (lane & 15);
    const uint32_t aBase = sbase + (uint32_t)((aRow * PA + wg * 8) * 4) + ((lane >> 4) << 4);
    const int bRow = wn * 32 + ((lane >> 4) << 3) + (lane & 7);
    const uint32_t bBase = sbase + (uint32_t)((bRow * PA + wg * 8) * 4) + (((lane >> 3) & 1) << 4);

    const uint32_t aA1 = aBase + A1_OFF * 4;
    const uint32_t aA2 = aBase + A2_OFF * 4;
    const uint32_t bB1 = bBase + B1_OFF * 4;
    const uint32_t bB2 = bBase + B2_OFF * 4;
    const uint32_t MI_STEP = 16 * PA * 4;   // +16 rows

    // A fill mapping: row rA = tid>>2, f4 slots sA and sA+4
    const int rA = tid >> 2;
    const int sA = tid & 3;
    const int rB = rA, qB = sA;

    const float4* x4 = (const float4*)x;     // row pitch 1024 f4
    const size_t xo = (size_t)(t0 + rA) * 1024 + sA;

    // ---- prologue: fill stage 0 (subs u=0,1)
    {
#pragma unroll
        for (int u = 0; u < 2; u++) {
            const uint32_t sd = sbase + (u * SUB_W) * 4;
            const uint32_t doff = (rB * PA + 4 * qB) * 4;
            const size_t so = (size_t)rB * (D_MODEL / 2) + u * 16 + 4 * qB;
            CPASYNC16(sd + B1_OFF * 4 + doff, g_b1 + so);
            CPASYNC16(sd + B2_OFF * 4 + doff, g_b2 + so);
        }
        CPCOMMIT();
#pragma unroll
        for (int u = 0; u < 2; u++) {
            float4 v0 = x4[xo + u * 8];
            float4 v1 = x4[xo + u * 8 + 4];
            uint32_t* s = smw + u * SUB_W;
            uint2 h1, h2;
            split4(v0, h1, h2);
            *(uint2*)(s + A1_OFF + rA * PA + 2 * sA) = h1;
            *(uint2*)(s + A2_OFF + rA * PA + 2 * sA) = h2;
            split4(v1, h1, h2);
            *(uint2*)(s + A1_OFF + rA * PA + 2 * sA + 8) = h1;
            *(uint2*)(s + A2_OFF + rA * PA + 2 * sA + 8) = h2;
        }
        CPWAIT0();
    }
    __syncthreads();

    float acc[2][4][4];
#pragma unroll
    for (int mi = 0; mi < 2; mi++)
#pragma unroll
        for (int ni = 0; ni < 4; ni++)
#pragma unroll
            for (int j = 0; j < 4; j++) acc[mi][ni][j] = 0.0f;

    // ---- main loop: 64 iterations of 64-k, double-buffered, one bar each
    for (int c = 0; c < NCH64; c++) {
        float4 n0, n1, n2, n3;
        if (c + 1 < NCH64) {
            const uint32_t stb = sbase + (((c + 1) & 1) * STAGE_W) * 4;
#pragma unroll
            for (int u = 0; u < 2; u++) {
                const int q = 2 * (c + 1) + u;
                const uint32_t sd = stb + (u * SUB_W) * 4;
                const uint32_t doff = (rB * PA + 4 * qB) * 4;
                const size_t so = (size_t)rB * (D_MODEL / 2) + q * 16 + 4 * qB;
                CPASYNC16(sd + B1_OFF * 4 + doff, g_b1 + so);
                CPASYNC16(sd + B2_OFF * 4 + doff, g_b2 + so);
            }
            const size_t d0 = (size_t)(2 * (c + 1)) * 8;
            n0 = x4[xo + d0];      n1 = x4[xo + d0 + 4];
            n2 = x4[xo + d0 + 8];  n3 = x4[xo + d0 + 12];
        }
        CPCOMMIT();

        // compute both 32-k subs of current stage via ldmatrix
        const uint32_t stoff = ((c & 1) * STAGE_W) * 4;
#pragma unroll
        for (int u = 0; u < 2; u++) {
            const uint32_t so = stoff + (u * SUB_W) * 4;
            uint32_t a1[2][4], a2[2][4], bq1[2][4], bq2[2][4];
            LDSM4(a1[0], aA1 + so);
            LDSM4(a1[1], aA1 + so + MI_STEP);
            LDSM4(a2[0], aA2 + so);
            LDSM4(a2[1], aA2 + so + MI_STEP);
            LDSM4(bq1[0], bB1 + so);
            LDSM4(bq1[1], bB1 + so + MI_STEP);
            LDSM4(bq2[0], bB2 + so);
            LDSM4(bq2[1], bB2 + so + MI_STEP);
#pragma unroll
            for (int ni = 0; ni < 4; ni++) {
                uint32_t b1[2] = { bq1[ni >> 1][(ni & 1) * 2], bq1[ni >> 1][(ni & 1) * 2 + 1] };
                uint32_t b2[2] = { bq2[ni >> 1][(ni & 1) * 2], bq2[ni >> 1][(ni & 1) * 2 + 1] };
#pragma unroll
                for (int mi = 0; mi < 2; mi++) {
                    // main term: fp32 accumulate
                    MMAH(acc[mi][ni], a1[mi], b1);
                    // residual terms: fp16 accumulate, drained immediately
                    uint32_t r0, r1;
                    MMAH16_Z(r0, r1, a2[mi], b1);
                    MMAH16_C(r0, r1, a1[mi], b2);
                    {
                        float2 f0 = __half22float2(*reinterpret_cast<__half2*>(&r0));
                        float2 f1 = __half22float2(*reinterpret_cast<__half2*>(&r1));
                        acc[mi][ni][0] += f0.x;
                        acc[mi][ni][1] += f0.y;
                        acc[mi][ni][2] += f1.x;
                        acc[mi][ni][3] += f1.y;
                    }
                    // a2*b2 dropped: ~2^-22 relative, below noise floor
                }
            }
        }

        // A split + store for next chunk
        if (c + 1 < NCH64) {
            uint32_t* stn = smw + ((c + 1) & 1) * STAGE_W;
            uint2 h1, h2;
            uint32_t* s0 = stn;
            split4(n0, h1, h2);
            *(uint2*)(s0 + A1_OFF + rA * PA + 2 * sA) = h1;
            *(uint2*)(s0 + A2_OFF + rA * PA + 2 * sA) = h2;
            split4(n1, h1, h2);
            *(uint2*)(s0 + A1_OFF + rA * PA + 2 * sA + 8) = h1;
            *(uint2*)(s0 + A2_OFF + rA * PA + 2 * sA + 8) = h2;
            uint32_t* s1 = stn + SUB_W;
            split4(n2, h1, h2);
            *(uint2*)(s1 + A1_OFF + rA * PA + 2 * sA) = h1;
            *(uint2*)(s1 + A2_OFF + rA * PA + 2 * sA) = h2;
            split4(n3, h1, h2);
            *(uint2*)(s1 + A1_OFF + rA * PA + 2 * sA + 8) = h1;
            *(uint2*)(s1 + A2_OFF + rA * PA + 2 * sA + 8) = h2;
        }
        CPWAIT0();
        __syncthreads();
    }

    // ---- merge k-half accumulators into G[64][65] (overlays stage smem)
    float* G = dynsm;
    if (wg == 0) {
#pragma unroll
        for (int mi = 0; mi < 2; mi++)
#pragma unroll
            for (int ni = 0; ni < 4; ni++) {
                int tr = wm * 32 + mi * 16 + lr;
                int ec = wn * 32 + ni * 8 + 2 * lc;
                G[tr * 65 + ec]           = acc[mi][ni][0] * WDESCALE;
                G[tr * 65 + ec + 1]       = acc[mi][ni][1] * WDESCALE;
                G[(tr + 8) * 65 + ec]     = acc[mi][ni][2] * WDESCALE;
                G[(tr + 8) * 65 + ec + 1] = acc[mi][ni][3] * WDESCALE;
            }
    }
    __syncthreads();
    if (wg == 1) {
#pragma unroll
        for (int mi = 0; mi < 2; mi++)
#pragma unroll
            for (int ni = 0; ni < 4; ni++) {
                int tr = wm * 32 + mi * 16 + lr;
                int ec = wn * 32 + ni * 8 + 2 * lc;
                G[tr * 65 + ec]           += acc[mi][ni][0] * WDESCALE;
                G[tr * 65 + ec + 1]       += acc[mi][ni][1] * WDESCALE;
                G[(tr + 8) * 65 + ec]     += acc[mi][ni][2] * WDESCALE;
                G[(tr + 8) * 65 + ec + 1] += acc[mi][ni][3] * WDESCALE;
            }
    }
    __syncthreads();

    // ---- epilogue phase 1: per-token max + top2
    int i1 = 0, i2 = 0;
    if (tid < TM) {
        const float* row = G + tid * 65;
        float v1 = -INFINITY, v2 = -INFINITY;
#pragma unroll 8
        for (int e = 0; e < N_EXP; e++) {
            float v = row[e];
            if (v > v1)      { v2 = v1; i2 = i1; v1 = v; i1 = e; }
            else if (v > v2) { v2 = v;  i2 = e; }
        }
        s_m[tid] = v1;
    }
    __syncthreads();

    // ---- phase 2: all threads exponentiate
#pragma unroll
    for (int i = 0; i < (TM * N_EXP) / NTHR; i++) {
        int idx = tid + i * NTHR;
        int t = idx >> 6, e = idx & 63;
        G[t * 65 + e] = expf(G[t * 65 + e] - s_m[t]);
    }
    __syncthreads();

    // ---- phase 3: per-token sums + outputs
    if (tid < TM) {
        const float* row = G + tid * 65;
        float ssum = 0.0f;
#pragma unroll 8
        for (int e = 0; e < N_EXP; e++) ssum += row[e];
        s_inv[tid] = 1.0f / ssum;

        float e1 = row[i1], e2 = row[i2];
        float rn = 1.0f / (e1 + e2);
        int tg = t0 + tid;
        out[2 * tg]     = e1 * rn;
        out[2 * tg + 1] = e2 * rn;
        out[2 * N_TOKENS + 2 * tg]     = (float)i1;
        out[2 * N_TOKENS + 2 * tg + 1] = (float)i2;
        atomicAdd(&cb[i1], 1);
    }
    __syncthreads();

    // ---- phase 4: per-expert prob sums -> global
    if (tid < N_EXP) {
        float s = 0.0f;
#pragma unroll 8
        for (int t = 0; t < TM; t++) s += G[t * 65 + tid] * s_inv[t];
        atomicAdd(&g_psum[tid], s);
        atomicAdd(&g_cnt[tid], cb[tid]);
    }

    // ---- last CTA: loss + scratch reset
    if (tid == 0) {
        __threadfence();
        int t = atomicAdd(&g_ticket, 1);
        s_islast = (t == NCTA - 1) ? 1 : 0;
    }
    __syncthreads();
    if (s_islast) {
        __threadfence();
        if (tid < N_EXP) {
            float p = *(volatile float*)&g_psum[tid];
            int   f = *(volatile int*)&g_cnt[tid];
            s_red[tid] = (float)f * p;
            g_psum[tid] = 0.0f;
            g_cnt[tid]  = 0;
        }
        __syncthreads();
        for (int st = 32; st > 0; st >>= 1) {
            if (tid < st) s_red[tid] += s_red[tid + st];
            __syncthreads();
        }
        if (tid == 0) {
            out[4 * N_TOKENS] = LB_COEF * s_red[0] * (1.0f / N_TOKENS) * (1.0f / N_TOKENS);
            g_ticket = 0;
        }
    }
}

// ---------------- launch ----------------
extern "C" void kernel_launch(void* const* d_in, const int* in_sizes, int n_in,
                              void* d_out, int out_size)
{
    const float* x  = (const float*)d_in[0];
    const float* gw = (const float*)d_in[1];
    float* out = (float*)d_out;

    cudaFuncSetAttribute(router_kernel,
                         cudaFuncAttributeMaxDynamicSharedMemorySize, DYN_BYTES);

    prep_kernel<<<(N_EXP * (D_MODEL / 2) + 255) / 256, 256>>>(gw);
    router_kernel<<<NCTA, NTHR, DYN_BYTES>>>(x, out);
}

// round 17
// speedup vs baseline: 1.4807x; 1.1484x over previous
#include <cuda_runtime.h>
#include <cuda_fp16.h>
#include <math.h>
#include <stdint.h>

#define N_TOKENS 16384
#define D_MODEL  4096
#define N_EXP    64
#define LB_COEF  0.01f

#define NCH64  (D_MODEL / 64)      // 64 iterations of 64-k
#define TM     64
#define NCTA   (N_TOKENS / TM)     // 256
#define NTHR   256

// R10-proven sub-chunk layout (32 k): 4 regions of 64 rows x (16 pair-words + 4 pad)
#define PA      20
#define A1_OFF  0
#define A2_OFF  (64 * PA)          // 1280
#define B1_OFF  (2 * 64 * PA)      // 2560
#define B2_OFF  (3 * 64 * PA)      // 3840
#define SUB_W   (4 * 64 * PA)      // 5120 words = 20 KB
#define STAGE_W (2 * SUB_W)        // 10240 words = 40 KB (two 32-k subs)
#define DYN_BYTES (2 * STAGE_W * 4)   // 81920 B

#define WSCALE   256.0f
#define WDESCALE 0.00390625f       // 2^-8

// ---------------- helpers ----------------
static __device__ __forceinline__ uint32_t smem_u32(const void* p) {
    uint32_t a;
    asm("{ .reg .u64 t; cvta.to.shared.u64 t, %1; cvt.u32.u64 %0, t; }" : "=r"(a) : "l"(p));
    return a;
}
#define CPASYNC16(dst, src) \
    asm volatile("cp.async.cg.shared.global [%0], [%1], 16;" :: "r"(dst), "l"(src))
#define CPCOMMIT()  asm volatile("cp.async.commit_group;" ::: "memory")
#define CPWAIT0()   asm volatile("cp.async.wait_group 0;" ::: "memory")

#define LDSM4(r, addr)                                                        \
    asm volatile("ldmatrix.sync.aligned.m8n8.x4.shared.b16 {%0,%1,%2,%3}, [%4];" \
        : "=r"((r)[0]), "=r"((r)[1]), "=r"((r)[2]), "=r"((r)[3]) : "r"(addr))

// split float4 -> h1 pairs (uint2) + residual h2 pairs (uint2)
static __device__ __forceinline__ void split4(float4 v, uint2& h1, uint2& h2) {
    __half a0 = __float2half_rn(v.x);
    __half a1 = __float2half_rn(v.y);
    __half a2 = __float2half_rn(v.z);
    __half a3 = __float2half_rn(v.w);
    __half b0 = __float2half_rn(v.x - __half2float(a0));
    __half b1 = __float2half_rn(v.y - __half2float(a1));
    __half b2 = __float2half_rn(v.z - __half2float(a2));
    __half b3 = __float2half_rn(v.w - __half2float(a3));
    __half2 p01 = __halves2half2(a0, a1);
    __half2 p23 = __halves2half2(a2, a3);
    __half2 q01 = __halves2half2(b0, b1);
    __half2 q23 = __halves2half2(b2, b3);
    h1.x = *reinterpret_cast<uint32_t*>(&p01);
    h1.y = *reinterpret_cast<uint32_t*>(&p23);
    h2.x = *reinterpret_cast<uint32_t*>(&q01);
    h2.y = *reinterpret_cast<uint32_t*>(&q23);
}

#define MMAH(d, a, b)                                                    \
    asm volatile(                                                        \
        "mma.sync.aligned.m16n8k16.row.col.f32.f16.f16.f32 "             \
        "{%0,%1,%2,%3}, {%4,%5,%6,%7}, {%8,%9}, {%0,%1,%2,%3};"          \
        : "+f"((d)[0]), "+f"((d)[1]), "+f"((d)[2]), "+f"((d)[3])         \
        : "r"((a)[0]), "r"((a)[1]), "r"((a)[2]), "r"((a)[3]),            \
          "r"((b)[0]), "r"((b)[1]))

// ---------------- device scratch ----------------
__device__ uint32_t g_b1[N_EXP * (D_MODEL / 2)];   // pre-split gw*256, h1 pairs
__device__ uint32_t g_b2[N_EXP * (D_MODEL / 2)];   // residual h2 pairs
__device__ float g_psum[N_EXP];
__device__ int   g_cnt[N_EXP];
__device__ int   g_ticket;

// ---------------- prep: split gate_w*256 into f16 pair tables ----------------
__global__ void prep_kernel(const float* __restrict__ gw) {
    int i = blockIdx.x * blockDim.x + threadIdx.x;
    if (i < N_EXP * (D_MODEL / 2)) {
        float x0 = gw[2 * i]     * WSCALE;
        float x1 = gw[2 * i + 1] * WSCALE;
        __half a0 = __float2half_rn(x0);
        __half a1 = __float2half_rn(x1);
        __half b0 = __float2half_rn(x0 - __half2float(a0));
        __half b1 = __float2half_rn(x1 - __half2float(a1));
        __half2 p = __halves2half2(a0, a1);
        __half2 q = __halves2half2(b0, b1);
        g_b1[i] = *reinterpret_cast<uint32_t*>(&p);
        g_b2[i] = *reinterpret_cast<uint32_t*>(&q);
    }
}

// ---------------- fused GEMM (2xFP16 3-term, full-fragment prefetch) -----------
// 256 threads = 8 warps, 2 CTAs/SM. CTA tile 64x64. Warp tile 32x32 over one k16.
__global__ __launch_bounds__(NTHR, 2)
void router_kernel(const float* __restrict__ x,
                   float* __restrict__ out)
{
    extern __shared__ float dynsm[];
    __shared__ int   cb[N_EXP];
    __shared__ float s_red[N_EXP];
    __shared__ float s_m[TM];
    __shared__ float s_inv[TM];
    __shared__ int   s_islast;

    const int tid  = threadIdx.x;
    const int t0   = blockIdx.x * TM;
    const int lane = tid & 31;
    const int wid  = tid >> 5;
    const int wg   = wid >> 2;          // k16-half within each 32-k sub-chunk
    const int widg = wid & 3;
    const int wm   = widg >> 1;
    const int wn   = widg & 1;
    const int lr   = lane >> 2;
    const int lc   = lane & 3;

    if (tid < N_EXP) cb[tid] = 0;

    uint32_t* smw = (uint32_t*)dynsm;
    const uint32_t sbase = smem_u32(dynsm);

    // ---- loop-invariant ldmatrix lane addresses
    const int aRow = wm * 32 + (lane & 15);
    const uint32_t aBase = sbase + (uint32_t)((aRow * PA + wg * 8) * 4) + ((lane >> 4) << 4);
    const int bRow = wn * 32 + ((lane >> 4) << 3) + (lane & 7);
    const uint32_t bBase = sbase + (uint32_t)((bRow * PA + wg * 8) * 4) + (((lane >> 3) & 1) << 4);

    const uint32_t aA1 = aBase + A1_OFF * 4;
    const uint32_t aA2 = aBase + A2_OFF * 4;
    const uint32_t bB1 = bBase + B1_OFF * 4;
    const uint32_t bB2 = bBase + B2_OFF * 4;
    const uint32_t MI_STEP = 16 * PA * 4;   // +16 rows

    // A fill mapping: row rA = tid>>2, f4 slots sA and sA+4
    const int rA = tid >> 2;
    const int sA = tid & 3;
    const int rB = rA, qB = sA;

    const float4* x4 = (const float4*)x;     // row pitch 1024 f4
    const size_t xo = (size_t)(t0 + rA) * 1024 + sA;

    // ---- prologue: fill stage 0 (subs u=0,1)
    {
#pragma unroll
        for (int u = 0; u < 2; u++) {
            const uint32_t sd = sbase + (u * SUB_W) * 4;
            const uint32_t doff = (rB * PA + 4 * qB) * 4;
            const size_t so = (size_t)rB * (D_MODEL / 2) + u * 16 + 4 * qB;
            CPASYNC16(sd + B1_OFF * 4 + doff, g_b1 + so);
            CPASYNC16(sd + B2_OFF * 4 + doff, g_b2 + so);
        }
        CPCOMMIT();
#pragma unroll
        for (int u = 0; u < 2; u++) {
            float4 v0 = x4[xo + u * 8];
            float4 v1 = x4[xo + u * 8 + 4];
            uint32_t* s = smw + u * SUB_W;
            uint2 h1, h2;
            split4(v0, h1, h2);
            *(uint2*)(s + A1_OFF + rA * PA + 2 * sA) = h1;
            *(uint2*)(s + A2_OFF + rA * PA + 2 * sA) = h2;
            split4(v1, h1, h2);
            *(uint2*)(s + A1_OFF + rA * PA + 2 * sA + 8) = h1;
            *(uint2*)(s + A2_OFF + rA * PA + 2 * sA + 8) = h2;
        }
        CPWAIT0();
    }
    __syncthreads();

    float acc[2][4][4];
#pragma unroll
    for (int mi = 0; mi < 2; mi++)
#pragma unroll
        for (int ni = 0; ni < 4; ni++)
#pragma unroll
            for (int j = 0; j < 4; j++) acc[mi][ni][j] = 0.0f;

    // ---- main loop: 64 iterations of 64-k, double-buffered, one bar each
    for (int c = 0; c < NCH64; c++) {
        const uint32_t stoff = ((c & 1) * STAGE_W) * 4;

        // ---- PHASE 1: load ALL fragments for BOTH subs (tensor pipe fills as soon
        //      as sub0's 8 land; sub1's LDSMs overlap sub0's MMAs)
        uint32_t a1[2][2][4], a2[2][2][4], bq1[2][2][4], bq2[2][2][4];
#pragma unroll
        for (int u = 0; u < 2; u++) {
            const uint32_t so = stoff + (u * SUB_W) * 4;
            LDSM4(a1[u][0], aA1 + so);
            LDSM4(a1[u][1], aA1 + so + MI_STEP);
            LDSM4(a2[u][0], aA2 + so);
            LDSM4(a2[u][1], aA2 + so + MI_STEP);
            LDSM4(bq1[u][0], bB1 + so);
            LDSM4(bq1[u][1], bB1 + so + MI_STEP);
            LDSM4(bq2[u][0], bB2 + so);
            LDSM4(bq2[u][1], bB2 + so + MI_STEP);
        }

        // ---- PHASE 2: issue B(c+1) cp.async (hides under MMA block)
        if (c + 1 < NCH64) {
            const uint32_t stb = sbase + (((c + 1) & 1) * STAGE_W) * 4;
#pragma unroll
            for (int u = 0; u < 2; u++) {
                const int q = 2 * (c + 1) + u;
                const uint32_t sd = stb + (u * SUB_W) * 4;
                const uint32_t doff = (rB * PA + 4 * qB) * 4;
                const size_t so = (size_t)rB * (D_MODEL / 2) + q * 16 + 4 * qB;
                CPASYNC16(sd + B1_OFF * 4 + doff, g_b1 + so);
                CPASYNC16(sd + B2_OFF * 4 + doff, g_b2 + so);
            }
        }
        CPCOMMIT();

        // ---- PHASE 3: MMA sub0
#pragma unroll
        for (int ni = 0; ni < 4; ni++) {
            uint32_t b1[2] = { bq1[0][ni >> 1][(ni & 1) * 2], bq1[0][ni >> 1][(ni & 1) * 2 + 1] };
            uint32_t b2[2] = { bq2[0][ni >> 1][(ni & 1) * 2], bq2[0][ni >> 1][(ni & 1) * 2 + 1] };
#pragma unroll
            for (int mi = 0; mi < 2; mi++) {
                MMAH(acc[mi][ni], a1[0][mi], b1);
                MMAH(acc[mi][ni], a2[0][mi], b1);
                MMAH(acc[mi][ni], a1[0][mi], b2);
            }
        }

        // ---- PHASE 4: LDG A(c+1) (hides under MMA sub1; sub0 frag regs now dead)
        float4 n0, n1, n2, n3;
        if (c + 1 < NCH64) {
            const size_t d0 = (size_t)(2 * (c + 1)) * 8;
            n0 = x4[xo + d0];      n1 = x4[xo + d0 + 4];
            n2 = x4[xo + d0 + 8];  n3 = x4[xo + d0 + 12];
        }

        // ---- PHASE 5: MMA sub1
#pragma unroll
        for (int ni = 0; ni < 4; ni++) {
            uint32_t b1[2] = { bq1[1][ni >> 1][(ni & 1) * 2], bq1[1][ni >> 1][(ni & 1) * 2 + 1] };
            uint32_t b2[2] = { bq2[1][ni >> 1][(ni & 1) * 2], bq2[1][ni >> 1][(ni & 1) * 2 + 1] };
#pragma unroll
            for (int mi = 0; mi < 2; mi++) {
                MMAH(acc[mi][ni], a1[1][mi], b1);
                MMAH(acc[mi][ni], a2[1][mi], b1);
                MMAH(acc[mi][ni], a1[1][mi], b2);
            }
        }

        // ---- PHASE 6: A(c+1) split + STS
        if (c + 1 < NCH64) {
            uint32_t* stn = smw + ((c + 1) & 1) * STAGE_W;
            uint2 h1, h2;
            uint32_t* s0 = stn;
            split4(n0, h1, h2);
            *(uint2*)(s0 + A1_OFF + rA * PA + 2 * sA) = h1;
            *(uint2*)(s0 + A2_OFF + rA * PA + 2 * sA) = h2;
            split4(n1, h1, h2);
            *(uint2*)(s0 + A1_OFF + rA * PA + 2 * sA + 8) = h1;
            *(uint2*)(s0 + A2_OFF + rA * PA + 2 * sA + 8) = h2;
            uint32_t* s1 = stn + SUB_W;
            split4(n2, h1, h2);
            *(uint2*)(s1 + A1_OFF + rA * PA + 2 * sA) = h1;
            *(uint2*)(s1 + A2_OFF + rA * PA + 2 * sA) = h2;
            split4(n3, h1, h2);
            *(uint2*)(s1 + A1_OFF + rA * PA + 2 * sA + 8) = h1;
            *(uint2*)(s1 + A2_OFF + rA * PA + 2 * sA + 8) = h2;
        }
        CPWAIT0();
        __syncthreads();
    }

    // ---- merge k-half accumulators into G[64][65] (overlays stage smem)
    float* G = dynsm;
    if (wg == 0) {
#pragma unroll
        for (int mi = 0; mi < 2; mi++)
#pragma unroll
            for (int ni = 0; ni < 4; ni++) {
                int tr = wm * 32 + mi * 16 + lr;
                int ec = wn * 32 + ni * 8 + 2 * lc;
                G[tr * 65 + ec]           = acc[mi][ni][0] * WDESCALE;
                G[tr * 65 + ec + 1]       = acc[mi][ni][1] * WDESCALE;
                G[(tr + 8) * 65 + ec]     = acc[mi][ni][2] * WDESCALE;
                G[(tr + 8) * 65 + ec + 1] = acc[mi][ni][3] * WDESCALE;
            }
    }
    __syncthreads();
    if (wg == 1) {
#pragma unroll
        for (int mi = 0; mi < 2; mi++)
#pragma unroll
            for (int ni = 0; ni < 4; ni++) {
                int tr = wm * 32 + mi * 16 + lr;
                int ec = wn * 32 + ni * 8 + 2 * lc;
                G[tr * 65 + ec]           += acc[mi][ni][0] * WDESCALE;
                G[tr * 65 + ec + 1]       += acc[mi][ni][1] * WDESCALE;
                G[(tr + 8) * 65 + ec]     += acc[mi][ni][2] * WDESCALE;
                G[(tr + 8) * 65 + ec + 1] += acc[mi][ni][3] * WDESCALE;
            }
    }
    __syncthreads();

    // ---- epilogue phase 1: per-token max + top2
    int i1 = 0, i2 = 0;
    if (tid < TM) {
        const float* row = G + tid * 65;
        float v1 = -INFINITY, v2 = -INFINITY;
#pragma unroll 8
        for (int e = 0; e < N_EXP; e++) {
            float v = row[e];
            if (v > v1)      { v2 = v1; i2 = i1; v1 = v; i1 = e; }
            else if (v > v2) { v2 = v;  i2 = e; }
        }
        s_m[tid] = v1;
    }
    __syncthreads();

    // ---- phase 2: all threads exponentiate
#pragma unroll
    for (int i = 0; i < (TM * N_EXP) / NTHR; i++) {
        int idx = tid + i * NTHR;
        int t = idx >> 6, e = idx & 63;
        G[t * 65 + e] = expf(G[t * 65 + e] - s_m[t]);
    }
    __syncthreads();

    // ---- phase 3: per-token sums + outputs
    if (tid < TM) {
        const float* row = G + tid * 65;
        float ssum = 0.0f;
#pragma unroll 8
        for (int e = 0; e < N_EXP; e++) ssum += row[e];
        s_inv[tid] = 1.0f / ssum;

        float e1 = row[i1], e2 = row[i2];
        float rn = 1.0f / (e1 + e2);
        int tg = t0 + tid;
        out[2 * tg]     = e1 * rn;
        out[2 * tg + 1] = e2 * rn;
        out[2 * N_TOKENS + 2 * tg]     = (float)i1;
        out[2 * N_TOKENS + 2 * tg + 1] = (float)i2;
        atomicAdd(&cb[i1], 1);
    }
    __syncthreads();

    // ---- phase 4: per-expert prob sums -> global
    if (tid < N_EXP) {
        float s = 0.0f;
#pragma unroll 8
        for (int t = 0; t < TM; t++) s += G[t * 65 + tid] * s_inv[t];
        atomicAdd(&g_psum[tid], s);
        atomicAdd(&g_cnt[tid], cb[tid]);
    }

    // ---- last CTA: loss + scratch reset
    if (tid == 0) {
        __threadfence();
        int t = atomicAdd(&g_ticket, 1);
        s_islast = (t == NCTA - 1) ? 1 : 0;
    }
    __syncthreads();
    if (s_islast) {
        __threadfence();
        if (tid < N_EXP) {
            float p = *(volatile float*)&g_psum[tid];
            int   f = *(volatile int*)&g_cnt[tid];
            s_red[tid] = (float)f * p;
            g_psum[tid] = 0.0f;
            g_cnt[tid]  = 0;
        }
        __syncthreads();
        for (int st = 32; st > 0; st >>= 1) {
            if (tid < st) s_red[tid] += s_red[tid + st];
            __syncthreads();
        }
        if (tid == 0) {
            out[4 * N_TOKENS] = LB_COEF * s_red[0] * (1.0f / N_TOKENS) * (1.0f / N_TOKENS);
            g_ticket = 0;
        }
    }
}

// ---------------- launch ----------------
extern "C" void kernel_launch(void* const* d_in, const int* in_sizes, int n_in,
                              void* d_out, int out_size)
{
    const float* x  = (const float*)d_in[0];
    const float* gw = (const float*)d_in[1];
    float* out = (float*)d_out;

    cudaFuncSetAttribute(router_kernel,
                         cudaFuncAttributeMaxDynamicSharedMemorySize, DYN_BYTES);

    prep_kernel<<<(N_EXP * (D_MODEL / 2) + 255) / 256, 256>>>(gw);
    router_kernel<<<NCTA, NTHR, DYN_BYTES>>>(x, out);
}